// round 2
// baseline (speedup 1.0000x reference)
#include <cuda_runtime.h>
#include <cuda_bf16.h>
#include <math.h>

// ---------------------------------------------------------------------------
// GAT layer: out[n] = (sum_{e: dst=n} w_e * msg[src_e]) / max(sum w_e, eps)
//   msg = x @ W^T ; w_e = exp(leaky_relu(s_src[src]+s_dst[dst], 0.01))
//   s_src = msg @ a[:F], s_dst = msg @ a[F:]
// Strategy: SMEM-resident-W SGEMM, then counting-sort edges by dst (CSR) and
// a warp-per-node gather (no float atomics anywhere).
// ---------------------------------------------------------------------------

#define MAXN   50048
#define MAXE   600064
#define MAXET  (MAXN + MAXE)
#define F      128

__device__ float g_msg[(size_t)MAXN * F];
__device__ float g_ssrc[MAXN];
__device__ float g_sdst[MAXN];
__device__ int   g_deg[MAXN];
__device__ int   g_off[MAXN + 1];
__device__ int   g_cur[MAXN];
__device__ int   g_srcs[MAXET];
__device__ float g_ws[MAXET];
__device__ int   g_is64;

// ---------------- dtype detect: int64 edge_index has zero high words --------
__global__ void k_detect(const int* ei32) {
    __shared__ int sh[256];
    int any = 0;
    for (int i = threadIdx.x; i < 512; i += 256) any |= ei32[2 * i + 1];
    sh[threadIdx.x] = any;
    __syncthreads();
    for (int s = 128; s > 0; s >>= 1) {
        if (threadIdx.x < s) sh[threadIdx.x] |= sh[threadIdx.x + s];
        __syncthreads();
    }
    if (threadIdx.x == 0) g_is64 = (sh[0] == 0) ? 1 : 0;
}

__device__ __forceinline__ void load_edge(const void* ei, int E, int e,
                                          int& src, int& dst) {
    if (g_is64) {
        const long long* p = (const long long*)ei;
        src = (int)p[e];
        dst = (int)p[E + e];
    } else {
        const int* p = (const int*)ei;
        src = p[e];
        dst = p[E + e];
    }
}

// ---------------- GEMM: msg = x @ W^T, plus s_src/s_dst --------------------
// 128 threads (thread = output feature), W kept in SMEM [f][k] padded to 132,
// 4 nodes per inner pass, 8 passes per block (32 nodes/block).
#define WPAD 132
#define GEMM_SMEM_BYTES ((F * WPAD + 4 * F) * (int)sizeof(float))

__global__ void k_gemm(const float* __restrict__ x, const float* __restrict__ W,
                       const float* __restrict__ a, int N) {
    extern __shared__ float smem[];
    float* Ws = smem;              // F * WPAD
    float* xs = smem + F * WPAD;   // 4 * F
    __shared__ float red[4][4][2];

    const int tid  = threadIdx.x;      // == feature f
    const int warp = tid >> 5;
    const int lane = tid & 31;
    const float a0 = a[tid];
    const float a1 = a[tid + F];

    for (int idx = tid; idx < F * F; idx += 128) {
        int ff = idx >> 7, kk = idx & 127;
        Ws[ff * WPAD + kk] = W[idx];
    }
    __syncthreads();

    const int nbase = blockIdx.x * 32;
    const float* wr = Ws + tid * WPAD;

    for (int g = 0; g < 8; ++g) {
        const int n0 = nbase + g * 4;
        for (int i = tid; i < 4 * F; i += 128) {
            int r = i >> 7, c = i & 127;
            int n = n0 + r;
            xs[r * F + c] = (n < N) ? x[(size_t)n * F + c] : 0.f;
        }
        __syncthreads();

        float acc[4] = {0.f, 0.f, 0.f, 0.f};
        #pragma unroll
        for (int k = 0; k < F; k += 4) {
            float4 wv = *(const float4*)(wr + k);
            float4 x0 = *(const float4*)(xs + 0 * F + k);
            float4 x1 = *(const float4*)(xs + 1 * F + k);
            float4 x2 = *(const float4*)(xs + 2 * F + k);
            float4 x3 = *(const float4*)(xs + 3 * F + k);
            acc[0] += wv.x * x0.x + wv.y * x0.y + wv.z * x0.z + wv.w * x0.w;
            acc[1] += wv.x * x1.x + wv.y * x1.y + wv.z * x1.z + wv.w * x1.w;
            acc[2] += wv.x * x2.x + wv.y * x2.y + wv.z * x2.z + wv.w * x2.w;
            acc[3] += wv.x * x3.x + wv.y * x3.y + wv.z * x3.z + wv.w * x3.w;
        }

        #pragma unroll
        for (int r = 0; r < 4; ++r) {
            if (n0 + r < N) g_msg[(size_t)(n0 + r) * F + tid] = acc[r];
            float p = acc[r] * a0;
            float q = acc[r] * a1;
            #pragma unroll
            for (int off = 16; off > 0; off >>= 1) {
                p += __shfl_down_sync(0xffffffffu, p, off);
                q += __shfl_down_sync(0xffffffffu, q, off);
            }
            if (lane == 0) { red[warp][r][0] = p; red[warp][r][1] = q; }
        }
        __syncthreads();
        if (tid < 8) {
            int r = tid >> 1, which = tid & 1;
            float s = red[0][r][which] + red[1][r][which] +
                      red[2][r][which] + red[3][r][which];
            if (n0 + r < N) {
                if (which) g_sdst[n0 + r] = s; else g_ssrc[n0 + r] = s;
            }
        }
        __syncthreads();
    }
}

// ---------------- CSR build ------------------------------------------------
__global__ void k_zero(int N) {
    int i = blockIdx.x * blockDim.x + threadIdx.x;
    if (i < N) g_deg[i] = 0;
}

__global__ void k_deg(const void* ei, int E, int ET) {
    int e = blockIdx.x * blockDim.x + threadIdx.x;
    if (e >= ET) return;
    int src, dst;
    if (e < E) load_edge(ei, E, e, src, dst);
    else       dst = e - E;
    atomicAdd(&g_deg[dst], 1);
}

__global__ void k_scan(int n) {
    __shared__ int sh[1024];
    __shared__ int s_carry;
    int tid = threadIdx.x;
    if (tid == 0) s_carry = 0;
    __syncthreads();
    for (int base = 0; base < n; base += 1024) {
        int v = (base + tid < n) ? g_deg[base + tid] : 0;
        sh[tid] = v;
        __syncthreads();
        for (int off = 1; off < 1024; off <<= 1) {
            int t = (tid >= off) ? sh[tid - off] : 0;
            __syncthreads();
            sh[tid] += t;
            __syncthreads();
        }
        int carry = s_carry;
        int excl = carry + sh[tid] - v;
        if (base + tid < n) { g_off[base + tid] = excl; g_cur[base + tid] = excl; }
        __syncthreads();
        if (tid == 1023) s_carry = carry + sh[1023];
        __syncthreads();
    }
    if (tid == 0) g_off[n] = s_carry;
}

__global__ void k_scatter(const void* ei, int E, int ET) {
    int e = blockIdx.x * blockDim.x + threadIdx.x;
    if (e >= ET) return;
    int src, dst;
    if (e < E) load_edge(ei, E, e, src, dst);
    else       src = dst = e - E;
    float s  = g_ssrc[src] + g_sdst[dst];
    float lr = (s > 0.f) ? s : 0.01f * s;
    float w  = expf(lr);
    int pos = atomicAdd(&g_cur[dst], 1);
    g_srcs[pos] = src;
    g_ws[pos]   = w;
}

// ---------------- gather: one warp per dst node ----------------------------
__global__ void k_gather(float* __restrict__ out, int N) {
    int gwarp = (blockIdx.x * blockDim.x + threadIdx.x) >> 5;
    int lane  = threadIdx.x & 31;
    if (gwarp >= N) return;
    int beg = g_off[gwarp];
    int end = g_off[gwarp + 1];
    float4 acc = make_float4(0.f, 0.f, 0.f, 0.f);
    float denom = 0.f;
    for (int e = beg; e < end; ++e) {
        int   s = g_srcs[e];
        float w = g_ws[e];
        denom += w;
        const float4 mv =
            *reinterpret_cast<const float4*>(&g_msg[(size_t)s * F + lane * 4]);
        acc.x += w * mv.x;
        acc.y += w * mv.y;
        acc.z += w * mv.z;
        acc.w += w * mv.w;
    }
    float inv = 1.f / fmaxf(denom, 1e-12f);
    float4 o = make_float4(acc.x * inv, acc.y * inv, acc.z * inv, acc.w * inv);
    *reinterpret_cast<float4*>(&out[(size_t)gwarp * F + lane * 4]) = o;
}

// ---------------------------------------------------------------------------
extern "C" void kernel_launch(void* const* d_in, const int* in_sizes, int n_in,
                              void* d_out, int out_size) {
    const float* x  = (const float*)d_in[0];
    const void*  ei = d_in[1];
    const float* W  = (const float*)d_in[2];
    const float* a  = (const float*)d_in[3];
    float* out = (float*)d_out;

    int N  = in_sizes[0] / F;
    int E  = in_sizes[1] / 2;
    int ET = E + N;

    cudaFuncSetAttribute(k_gemm, cudaFuncAttributeMaxDynamicSharedMemorySize,
                         GEMM_SMEM_BYTES);

    k_detect<<<1, 256>>>((const int*)ei);
    k_gemm<<<(N + 31) / 32, 128, GEMM_SMEM_BYTES>>>(x, W, a, N);
    k_zero<<<(N + 255) / 256, 256>>>(N);
    k_deg<<<(ET + 255) / 256, 256>>>(ei, E, ET);
    k_scan<<<1, 1024>>>(N);
    k_scatter<<<(ET + 255) / 256, 256>>>(ei, E, ET);
    k_gather<<<(N + 7) / 8, 256>>>(out, N);
}

// round 4
// speedup vs baseline: 1.6505x; 1.6505x over previous
#include <cuda_runtime.h>
#include <cuda_bf16.h>
#include <math.h>

// ---------------------------------------------------------------------------
// GAT layer on GB300.
//  msg = x @ W^T  (tf32x2 tensor-core GEMM, fp32-accurate)
//  s_src = msg@a[:F], s_dst = msg@a[F:]  (fused into GEMM epilogue)
//  CSR-by-dst build (histogram -> shuffle scan -> counting sort)
//  warp-per-node gather (no float atomics)
// ---------------------------------------------------------------------------

#define MAXN   50048
#define MAXE   600064
#define MAXET  (MAXN + MAXE)
#define F      128
#define PAD    132

__device__ float g_msg[(size_t)MAXN * F];
__device__ float g_ssrc[MAXN];
__device__ float g_sdst[MAXN];
__device__ int   g_deg[MAXN];
__device__ int   g_off[MAXN + 1];
__device__ int   g_cur[MAXN];
__device__ int   g_srcs[MAXET];
__device__ float g_ws[MAXET];
__device__ int   g_is64;

// ---------------- init: zero degree histogram + edge dtype detect ----------
__global__ void k_init(const int* __restrict__ ei32, int N) {
    __shared__ int sh[256];
    int i = blockIdx.x * blockDim.x + threadIdx.x;
    if (i < N) g_deg[i] = 0;
    if (blockIdx.x == 0) {
        int any = 0;
        for (int t = threadIdx.x; t < 512; t += 256) any |= ei32[2 * t + 1];
        sh[threadIdx.x] = any;
        __syncthreads();
        for (int s = 128; s > 0; s >>= 1) {
            if (threadIdx.x < s) sh[threadIdx.x] |= sh[threadIdx.x + s];
            __syncthreads();
        }
        if (threadIdx.x == 0) g_is64 = (sh[0] == 0) ? 1 : 0;
    }
}

__device__ __forceinline__ void load_edge(const void* ei, int E, int e,
                                          int& src, int& dst) {
    if (g_is64) {
        const long long* p = (const long long*)ei;
        src = (int)p[e];
        dst = (int)p[E + e];
    } else {
        const int* p = (const int*)ei;
        src = p[e];
        dst = p[E + e];
    }
}

// ---------------- tf32 helpers ---------------------------------------------
__device__ __forceinline__ unsigned f2tf(float f) {
    unsigned u;
    asm("cvt.rna.tf32.f32 %0, %1;" : "=r"(u) : "f"(f));
    return u;
}

__device__ __forceinline__ void mma8(float* c,
                                     unsigned a0, unsigned a1, unsigned a2, unsigned a3,
                                     unsigned b0, unsigned b1) {
    asm volatile(
        "mma.sync.aligned.m16n8k8.row.col.f32.tf32.tf32.f32 "
        "{%0,%1,%2,%3}, {%4,%5,%6,%7}, {%8,%9}, {%0,%1,%2,%3};\n"
        : "+f"(c[0]), "+f"(c[1]), "+f"(c[2]), "+f"(c[3])
        : "r"(a0), "r"(a1), "r"(a2), "r"(a3), "r"(b0), "r"(b1));
}

// ---------------- GEMM: msg = x @ W^T (tf32x2), + s_src/s_dst --------------
// Block: 128 nodes x 128 feats, 256 threads (8 warps), each warp 16 rows.
#define GEMM_SMEM_BYTES ((2 * F * PAD + 2 * F) * (int)sizeof(float))

__global__ void k_gemm(const float* __restrict__ x, const float* __restrict__ W,
                       const float* __restrict__ a, int N) {
    extern __shared__ float smem[];
    float* As = smem;               // F x PAD (x tile, later reused for output)
    float* Ws = smem + F * PAD;     // F x PAD
    float* av = smem + 2 * F * PAD; // 2F

    const int tid  = threadIdx.x;
    const int warp = tid >> 5;
    const int lane = tid & 31;
    const int g    = lane >> 2;      // 0..7
    const int tg   = lane & 3;       // 0..3
    const int m0   = blockIdx.x * 128;

    if (tid < 256) av[tid] = a[tid];
    for (int idx = tid; idx < F * 32; idx += 256) {
        int r = idx >> 5, c4 = idx & 31;
        float4 v = ((const float4*)W)[idx];
        *(float4*)&Ws[r * PAD + c4 * 4] = v;
    }
    for (int idx = tid; idx < F * 32; idx += 256) {
        int r = idx >> 5, c4 = idx & 31;
        int row = m0 + r;
        float4 v = (row < N) ? ((const float4*)x)[(size_t)row * 32 + c4]
                             : make_float4(0.f, 0.f, 0.f, 0.f);
        *(float4*)&As[r * PAD + c4 * 4] = v;
    }
    __syncthreads();

    float acc[16][4];
    #pragma unroll
    for (int j = 0; j < 16; ++j)
        acc[j][0] = acc[j][1] = acc[j][2] = acc[j][3] = 0.f;

    const int mw = warp * 16;

    #pragma unroll
    for (int ka = 0; ka < 16; ++ka) {
        const int k0 = ka * 8;
        float a0f = As[(mw + g)     * PAD + k0 + tg];
        float a1f = As[(mw + g + 8) * PAD + k0 + tg];
        float a2f = As[(mw + g)     * PAD + k0 + tg + 4];
        float a3f = As[(mw + g + 8) * PAD + k0 + tg + 4];
        unsigned ah0 = f2tf(a0f), ah1 = f2tf(a1f), ah2 = f2tf(a2f), ah3 = f2tf(a3f);
        unsigned al0 = f2tf(a0f - __uint_as_float(ah0));
        unsigned al1 = f2tf(a1f - __uint_as_float(ah1));
        unsigned al2 = f2tf(a2f - __uint_as_float(ah2));
        unsigned al3 = f2tf(a3f - __uint_as_float(ah3));

        #pragma unroll
        for (int j = 0; j < 16; ++j) {
            float b0f = Ws[(8 * j + g) * PAD + k0 + tg];
            float b1f = Ws[(8 * j + g) * PAD + k0 + tg + 4];
            unsigned bh0 = f2tf(b0f), bh1 = f2tf(b1f);
            unsigned bl0 = f2tf(b0f - __uint_as_float(bh0));
            unsigned bl1 = f2tf(b1f - __uint_as_float(bh1));
            mma8(acc[j], ah0, ah1, ah2, ah3, bh0, bh1);  // hi*hi
            mma8(acc[j], ah0, ah1, ah2, ah3, bl0, bl1);  // hi*lo
            mma8(acc[j], al0, al1, al2, al3, bh0, bh1);  // lo*hi
        }
    }

    // ---- fused attention scores: s = msg @ a -------------------------------
    float p0 = 0.f, q0 = 0.f, p1 = 0.f, q1 = 0.f;  // rows g, g+8
    #pragma unroll
    for (int j = 0; j < 16; ++j) {
        int c = 8 * j + 2 * tg;
        p0 += acc[j][0] * av[c]       + acc[j][1] * av[c + 1];
        q0 += acc[j][0] * av[F + c]   + acc[j][1] * av[F + c + 1];
        p1 += acc[j][2] * av[c]       + acc[j][3] * av[c + 1];
        q1 += acc[j][2] * av[F + c]   + acc[j][3] * av[F + c + 1];
    }
    #pragma unroll
    for (int off = 1; off < 4; off <<= 1) {
        p0 += __shfl_xor_sync(0xffffffffu, p0, off);
        q0 += __shfl_xor_sync(0xffffffffu, q0, off);
        p1 += __shfl_xor_sync(0xffffffffu, p1, off);
        q1 += __shfl_xor_sync(0xffffffffu, q1, off);
    }
    if (tg == 0) {
        int r0 = m0 + mw + g, r1 = r0 + 8;
        if (r0 < N) { g_ssrc[r0] = p0; g_sdst[r0] = q0; }
        if (r1 < N) { g_ssrc[r1] = p1; g_sdst[r1] = q1; }
    }

    // ---- stage accumulators to (warp-private) SMEM, store coalesced --------
    __syncwarp();
    #pragma unroll
    for (int j = 0; j < 16; ++j) {
        int c = 8 * j + 2 * tg;
        *(float2*)&As[(mw + g)     * PAD + c] = make_float2(acc[j][0], acc[j][1]);
        *(float2*)&As[(mw + g + 8) * PAD + c] = make_float2(acc[j][2], acc[j][3]);
    }
    __syncwarp();
    for (int idx = lane; idx < 512; idx += 32) {
        int r = idx >> 5, c4 = idx & 31;
        int row = m0 + mw + r;
        if (row < N)
            *(float4*)&g_msg[(size_t)row * F + c4 * 4] =
                *(float4*)&As[(mw + r) * PAD + c4 * 4];
    }
}

// ---------------- CSR build ------------------------------------------------
__global__ void k_deg(const void* ei, int E, int ET) {
    int e = blockIdx.x * blockDim.x + threadIdx.x;
    if (e >= ET) return;
    int src, dst;
    if (e < E) load_edge(ei, E, e, src, dst);
    else       dst = e - E;
    atomicAdd(&g_deg[dst], 1);
}

// Shuffle-based block-wide scan, single block iterates over chunks of 1024.
__global__ void k_scan(int n) {
    __shared__ int wsum[32];
    __shared__ int s_carry;
    const int tid = threadIdx.x;
    const int warp = tid >> 5, lane = tid & 31;
    if (tid == 0) s_carry = 0;
    __syncthreads();
    for (int base = 0; base < n; base += 1024) {
        int v = (base + tid < n) ? g_deg[base + tid] : 0;
        int s = v;
        #pragma unroll
        for (int off = 1; off < 32; off <<= 1) {
            int t = __shfl_up_sync(0xffffffffu, s, off);
            if (lane >= off) s += t;
        }
        if (lane == 31) wsum[warp] = s;
        __syncthreads();
        if (warp == 0) {
            int ws = wsum[lane];
            #pragma unroll
            for (int off = 1; off < 32; off <<= 1) {
                int t = __shfl_up_sync(0xffffffffu, ws, off);
                if (lane >= off) ws += t;
            }
            wsum[lane] = ws;
        }
        __syncthreads();
        int blockoff = s_carry + (warp ? wsum[warp - 1] : 0);
        int excl = blockoff + s - v;
        if (base + tid < n) { g_off[base + tid] = excl; g_cur[base + tid] = excl; }
        __syncthreads();
        if (tid == 1023) s_carry = blockoff + s;
        __syncthreads();
    }
    if (tid == 0) g_off[n] = s_carry;
}

__global__ void k_scatter(const void* ei, int E, int ET) {
    int e = blockIdx.x * blockDim.x + threadIdx.x;
    if (e >= ET) return;
    int src, dst;
    if (e < E) load_edge(ei, E, e, src, dst);
    else       src = dst = e - E;
    float s  = g_ssrc[src] + g_sdst[dst];
    float lr = (s > 0.f) ? s : 0.01f * s;
    float w  = expf(lr);
    int pos = atomicAdd(&g_cur[dst], 1);
    g_srcs[pos] = src;
    g_ws[pos]   = w;
}

// ---------------- gather: one warp per dst node ----------------------------
__global__ void k_gather(float* __restrict__ out, int N) {
    int gw   = (blockIdx.x * blockDim.x + threadIdx.x) >> 5;
    int lane = threadIdx.x & 31;
    if (gw >= N) return;
    int beg = g_off[gw];
    int end = g_off[gw + 1];
    float4 acc = make_float4(0.f, 0.f, 0.f, 0.f);
    float denom = 0.f;
    int e = beg;
    for (; e + 2 <= end; e += 2) {
        int   s0 = g_srcs[e],     s1 = g_srcs[e + 1];
        float w0 = g_ws[e],       w1 = g_ws[e + 1];
        const float4 m0 = *(const float4*)&g_msg[(size_t)s0 * F + lane * 4];
        const float4 m1 = *(const float4*)&g_msg[(size_t)s1 * F + lane * 4];
        denom += w0 + w1;
        acc.x += w0 * m0.x + w1 * m1.x;
        acc.y += w0 * m0.y + w1 * m1.y;
        acc.z += w0 * m0.z + w1 * m1.z;
        acc.w += w0 * m0.w + w1 * m1.w;
    }
    if (e < end) {
        int   s0 = g_srcs[e];
        float w0 = g_ws[e];
        const float4 m0 = *(const float4*)&g_msg[(size_t)s0 * F + lane * 4];
        denom += w0;
        acc.x += w0 * m0.x; acc.y += w0 * m0.y;
        acc.z += w0 * m0.z; acc.w += w0 * m0.w;
    }
    float inv = 1.f / fmaxf(denom, 1e-12f);
    float4 o = make_float4(acc.x * inv, acc.y * inv, acc.z * inv, acc.w * inv);
    *reinterpret_cast<float4*>(&out[(size_t)gw * F + lane * 4]) = o;
}

// ---------------------------------------------------------------------------
extern "C" void kernel_launch(void* const* d_in, const int* in_sizes, int n_in,
                              void* d_out, int out_size) {
    const float* x  = (const float*)d_in[0];
    const void*  ei = d_in[1];
    const float* W  = (const float*)d_in[2];
    const float* a  = (const float*)d_in[3];
    float* out = (float*)d_out;

    int N  = in_sizes[0] / F;
    int E  = in_sizes[1] / 2;
    int ET = E + N;

    cudaFuncSetAttribute(k_gemm, cudaFuncAttributeMaxDynamicSharedMemorySize,
                         GEMM_SMEM_BYTES);

    k_init<<<(N + 255) / 256, 256>>>((const int*)ei, N);
    k_gemm<<<(N + 127) / 128, 256, GEMM_SMEM_BYTES>>>(x, W, a, N);
    k_deg<<<(ET + 255) / 256, 256>>>(ei, E, ET);
    k_scan<<<1, 1024>>>(N);
    k_scatter<<<(ET + 255) / 256, 256>>>(ei, E, ET);
    k_gather<<<(N + 7) / 8, 256>>>(out, N);
}

// round 7
// speedup vs baseline: 2.2570x; 1.3674x over previous
#include <cuda_runtime.h>
#include <cuda_bf16.h>
#include <math.h>

// ---------------------------------------------------------------------------
// GAT layer on GB300.
//  msg = x @ W^T  (tf32x2 tensor-core GEMM, W pre-converted to mma fragments)
//  s_src = msg@a[:F], s_dst = msg@a[F:]  (fused into GEMM epilogue)
//  CSR-by-dst build (histogram -> multi-block scan -> counting sort)
//  warp-per-node gather (no float atomics)
// ---------------------------------------------------------------------------

#define MAXN   50048
#define MAXE   600064
#define MAXET  (MAXN + MAXE)
#define F      128
#define PAD    132

__device__ float  g_msg[(size_t)MAXN * F];
__device__ float  g_ssrc[MAXN];
__device__ float  g_sdst[MAXN];
__device__ int    g_deg[MAXN];
__device__ int    g_off[MAXN + 1];
__device__ int    g_cur[MAXN];
__device__ float2 g_sw[MAXET];          // packed (src_bits, w)
__device__ int    g_bsum[64];
__device__ int    g_is64;
__device__ uint4  g_bfrag[16 * 16 * 32]; // per-(ka,j,lane) B fragments

// ---------------- init: zero degree histogram + edge dtype detect ----------
__global__ void k_init(const int* __restrict__ ei32, int N) {
    __shared__ int sh[256];
    int i = blockIdx.x * blockDim.x + threadIdx.x;
    if (i < N) g_deg[i] = 0;
    if (blockIdx.x == 0) {
        int any = 0;
        for (int t = threadIdx.x; t < 512; t += 256) any |= ei32[2 * t + 1];
        sh[threadIdx.x] = any;
        __syncthreads();
        for (int s = 128; s > 0; s >>= 1) {
            if (threadIdx.x < s) sh[threadIdx.x] |= sh[threadIdx.x + s];
            __syncthreads();
        }
        if (threadIdx.x == 0) g_is64 = (sh[0] == 0) ? 1 : 0;
    }
}

__device__ __forceinline__ void load_edge(const void* ei, int E, int e,
                                          int& src, int& dst) {
    if (g_is64) {
        const long long* p = (const long long*)ei;
        src = (int)p[e];
        dst = (int)p[E + e];
    } else {
        const int* p = (const int*)ei;
        src = p[e];
        dst = p[E + e];
    }
}

// ---------------- tf32 helpers ---------------------------------------------
__device__ __forceinline__ unsigned f2tf(float f) {
    unsigned u;
    asm("cvt.rna.tf32.f32 %0, %1;" : "=r"(u) : "f"(f));
    return u;
}

__device__ __forceinline__ void mma8(float* c,
                                     unsigned a0, unsigned a1, unsigned a2, unsigned a3,
                                     unsigned b0, unsigned b1) {
    asm volatile(
        "mma.sync.aligned.m16n8k8.row.col.f32.tf32.tf32.f32 "
        "{%0,%1,%2,%3}, {%4,%5,%6,%7}, {%8,%9}, {%0,%1,%2,%3};\n"
        : "+f"(c[0]), "+f"(c[1]), "+f"(c[2]), "+f"(c[3])
        : "r"(a0), "r"(a1), "r"(a2), "r"(a3), "r"(b0), "r"(b1));
}

// ---------------- W -> tf32x2 mma fragments --------------------------------
__global__ void k_wcvt(const float* __restrict__ W) {
    int t = blockIdx.x * blockDim.x + threadIdx.x;
    if (t >= 16 * 16 * 32) return;
    int lane = t & 31, j = (t >> 5) & 15, ka = t >> 9;
    int g = lane >> 2, tg = lane & 3;
    float b0 = W[(8 * j + g) * F + 8 * ka + tg];
    float b1 = W[(8 * j + g) * F + 8 * ka + tg + 4];
    unsigned bh0 = f2tf(b0), bh1 = f2tf(b1);
    unsigned bl0 = f2tf(b0 - __uint_as_float(bh0));
    unsigned bl1 = f2tf(b1 - __uint_as_float(bh1));
    g_bfrag[t] = make_uint4(bh0, bh1, bl0, bl1);
}

// ---------------- GEMM: msg = x @ W^T (tf32x2), + s_src/s_dst --------------
// Block: 128 nodes x 128 feats, 256 threads (8 warps), each warp 16 rows.
// SMEM: As (x tile, reused for output stage) + staged B fragments + a vector.
#define GEMM_SMEM_BYTES ((F * PAD + 2 * F) * (int)sizeof(float) + 16 * 16 * 32 * (int)sizeof(uint4))

__global__ void __launch_bounds__(256) k_gemm(const float* __restrict__ x,
                                              const float* __restrict__ a, int N) {
    extern __shared__ float smem[];
    float* As = smem;                              // F x PAD
    uint4* Bf = (uint4*)(smem + F * PAD);          // 8192 uint4
    float* av = smem + F * PAD + 16 * 16 * 32 * 4; // 2F floats

    const int tid  = threadIdx.x;
    const int warp = tid >> 5;
    const int lane = tid & 31;
    const int g    = lane >> 2;      // 0..7
    const int tg   = lane & 3;       // 0..3
    const int m0   = blockIdx.x * 128;

    if (tid < 256) av[tid] = a[tid];
    for (int idx = tid; idx < 16 * 16 * 32; idx += 256)
        Bf[idx] = g_bfrag[idx];
    for (int idx = tid; idx < F * 32; idx += 256) {
        int r = idx >> 5, c4 = idx & 31;
        int row = m0 + r;
        float4 v = (row < N) ? ((const float4*)x)[(size_t)row * 32 + c4]
                             : make_float4(0.f, 0.f, 0.f, 0.f);
        *(float4*)&As[r * PAD + c4 * 4] = v;
    }
    __syncthreads();

    float acc[16][4];
    #pragma unroll
    for (int j = 0; j < 16; ++j)
        acc[j][0] = acc[j][1] = acc[j][2] = acc[j][3] = 0.f;

    const int mw = warp * 16;

    #pragma unroll
    for (int ka = 0; ka < 16; ++ka) {
        const int k0 = ka * 8;
        float a0f = As[(mw + g)     * PAD + k0 + tg];
        float a1f = As[(mw + g + 8) * PAD + k0 + tg];
        float a2f = As[(mw + g)     * PAD + k0 + tg + 4];
        float a3f = As[(mw + g + 8) * PAD + k0 + tg + 4];
        unsigned ah0 = f2tf(a0f), ah1 = f2tf(a1f), ah2 = f2tf(a2f), ah3 = f2tf(a3f);
        unsigned al0 = f2tf(a0f - __uint_as_float(ah0));
        unsigned al1 = f2tf(a1f - __uint_as_float(ah1));
        unsigned al2 = f2tf(a2f - __uint_as_float(ah2));
        unsigned al3 = f2tf(a3f - __uint_as_float(ah3));

        #pragma unroll
        for (int j = 0; j < 16; ++j) {
            uint4 b = Bf[(ka * 16 + j) * 32 + lane];
            mma8(acc[j], ah0, ah1, ah2, ah3, b.x, b.y);  // hi*hi
            mma8(acc[j], ah0, ah1, ah2, ah3, b.z, b.w);  // hi*lo
            mma8(acc[j], al0, al1, al2, al3, b.x, b.y);  // lo*hi
        }
    }

    // ---- fused attention scores: s = msg @ a -------------------------------
    float p0 = 0.f, q0 = 0.f, p1 = 0.f, q1 = 0.f;  // rows g, g+8
    #pragma unroll
    for (int j = 0; j < 16; ++j) {
        int c = 8 * j + 2 * tg;
        p0 += acc[j][0] * av[c]       + acc[j][1] * av[c + 1];
        q0 += acc[j][0] * av[F + c]   + acc[j][1] * av[F + c + 1];
        p1 += acc[j][2] * av[c]       + acc[j][3] * av[c + 1];
        q1 += acc[j][2] * av[F + c]   + acc[j][3] * av[F + c + 1];
    }
    #pragma unroll
    for (int off = 1; off < 4; off <<= 1) {
        p0 += __shfl_xor_sync(0xffffffffu, p0, off);
        q0 += __shfl_xor_sync(0xffffffffu, q0, off);
        p1 += __shfl_xor_sync(0xffffffffu, p1, off);
        q1 += __shfl_xor_sync(0xffffffffu, q1, off);
    }
    if (tg == 0) {
        int r0 = m0 + mw + g, r1 = r0 + 8;
        if (r0 < N) { g_ssrc[r0] = p0; g_sdst[r0] = q0; }
        if (r1 < N) { g_ssrc[r1] = p1; g_sdst[r1] = q1; }
    }

    // ---- stage accumulators to (warp-private) SMEM, store coalesced --------
    __syncwarp();
    #pragma unroll
    for (int j = 0; j < 16; ++j) {
        int c = 8 * j + 2 * tg;
        *(float2*)&As[(mw + g)     * PAD + c] = make_float2(acc[j][0], acc[j][1]);
        *(float2*)&As[(mw + g + 8) * PAD + c] = make_float2(acc[j][2], acc[j][3]);
    }
    __syncwarp();
    for (int idx = lane; idx < 512; idx += 32) {
        int r = idx >> 5, c4 = idx & 31;
        int row = m0 + mw + r;
        if (row < N)
            *(float4*)&g_msg[(size_t)row * F + c4 * 4] =
                *(float4*)&As[(mw + r) * PAD + c4 * 4];
    }
}

// ---------------- CSR build ------------------------------------------------
__global__ void k_deg(const void* ei, int E, int ET) {
    int e = blockIdx.x * blockDim.x + threadIdx.x;
    if (e >= ET) return;
    int src, dst;
    if (e < E) load_edge(ei, E, e, src, dst);
    else       dst = e - E;
    atomicAdd(&g_deg[dst], 1);
}

// Multi-block scan, pass 1: per-block local exclusive scan + block totals.
__global__ void k_scan1(int n) {
    __shared__ int wsum[32];
    const int tid = threadIdx.x, lane = tid & 31, warp = tid >> 5;
    const int i = blockIdx.x * 1024 + tid;
    int v = (i < n) ? g_deg[i] : 0;
    int s = v;
    #pragma unroll
    for (int off = 1; off < 32; off <<= 1) {
        int t = __shfl_up_sync(0xffffffffu, s, off);
        if (lane >= off) s += t;
    }
    if (lane == 31) wsum[warp] = s;
    __syncthreads();
    if (warp == 0) {
        int ws = wsum[lane];
        #pragma unroll
        for (int off = 1; off < 32; off <<= 1) {
            int t = __shfl_up_sync(0xffffffffu, ws, off);
            if (lane >= off) ws += t;
        }
        wsum[lane] = ws;
    }
    __syncthreads();
    int excl = (warp ? wsum[warp - 1] : 0) + s - v;
    if (i < n) g_off[i] = excl;
    if (tid == 0) g_bsum[blockIdx.x] = wsum[31];
}

// Pass 2: exclusive scan of (<=64) block totals, one block.
__global__ void k_scan2(int nb) {
    __shared__ int sh[64];
    int tid = threadIdx.x;
    int v = (tid < nb) ? g_bsum[tid] : 0;
    sh[tid] = v;
    __syncthreads();
    #pragma unroll
    for (int off = 1; off < 64; off <<= 1) {
        int t = (tid >= off) ? sh[tid - off] : 0;
        __syncthreads();
        sh[tid] += t;
        __syncthreads();
    }
    if (tid < nb) g_bsum[tid] = sh[tid] - v;
}

// Pass 3: add block offsets, init cursors.
__global__ void k_scan3(int n, int total) {
    int i = blockIdx.x * 1024 + threadIdx.x;
    if (i < n) {
        int o = g_off[i] + g_bsum[blockIdx.x];
        g_off[i] = o;
        g_cur[i] = o;
    }
    if (i == 0) g_off[n] = total;
}

__global__ void k_scatter(const void* ei, int E, int ET) {
    int e = blockIdx.x * blockDim.x + threadIdx.x;
    if (e >= ET) return;
    int src, dst;
    if (e < E) load_edge(ei, E, e, src, dst);
    else       src = dst = e - E;
    float s  = g_ssrc[src] + g_sdst[dst];
    float lr = (s > 0.f) ? s : 0.01f * s;
    float w  = expf(lr);
    int pos = atomicAdd(&g_cur[dst], 1);
    g_sw[pos] = make_float2(__int_as_float(src), w);
}

// ---------------- gather: one warp per dst node ----------------------------
__global__ void k_gather(float* __restrict__ out, int N) {
    int gw   = (blockIdx.x * blockDim.x + threadIdx.x) >> 5;
    int lane = threadIdx.x & 31;
    if (gw >= N) return;
    int beg = g_off[gw];
    int end = g_off[gw + 1];
    float4 acc = make_float4(0.f, 0.f, 0.f, 0.f);
    float denom = 0.f;
    int e = beg;
    for (; e + 2 <= end; e += 2) {
        float2 sw0 = g_sw[e], sw1 = g_sw[e + 1];
        int   s0 = __float_as_int(sw0.x), s1 = __float_as_int(sw1.x);
        float w0 = sw0.y,                 w1 = sw1.y;
        const float4 m0 = *(const float4*)&g_msg[(size_t)s0 * F + lane * 4];
        const float4 m1 = *(const float4*)&g_msg[(size_t)s1 * F + lane * 4];
        denom += w0 + w1;
        acc.x += w0 * m0.x + w1 * m1.x;
        acc.y += w0 * m0.y + w1 * m1.y;
        acc.z += w0 * m0.z + w1 * m1.z;
        acc.w += w0 * m0.w + w1 * m1.w;
    }
    if (e < end) {
        float2 sw0 = g_sw[e];
        int   s0 = __float_as_int(sw0.x);
        float w0 = sw0.y;
        const float4 m0 = *(const float4*)&g_msg[(size_t)s0 * F + lane * 4];
        denom += w0;
        acc.x += w0 * m0.x; acc.y += w0 * m0.y;
        acc.z += w0 * m0.z; acc.w += w0 * m0.w;
    }
    float inv = 1.f / fmaxf(denom, 1e-12f);
    float4 o = make_float4(acc.x * inv, acc.y * inv, acc.z * inv, acc.w * inv);
    *reinterpret_cast<float4*>(&out[(size_t)gw * F + lane * 4]) = o;
}

// ---------------------------------------------------------------------------
extern "C" void kernel_launch(void* const* d_in, const int* in_sizes, int n_in,
                              void* d_out, int out_size) {
    const float* x  = (const float*)d_in[0];
    const void*  ei = d_in[1];
    const float* W  = (const float*)d_in[2];
    const float* a  = (const float*)d_in[3];
    float* out = (float*)d_out;

    int N  = in_sizes[0] / F;
    int E  = in_sizes[1] / 2;
    int ET = E + N;
    int NB = (N + 1023) / 1024;

    cudaFuncSetAttribute(k_gemm, cudaFuncAttributeMaxDynamicSharedMemorySize,
                         GEMM_SMEM_BYTES);

    k_init<<<(N + 255) / 256, 256>>>((const int*)ei, N);
    k_wcvt<<<8, 1024>>>(W);
    k_gemm<<<(N + 127) / 128, 256, GEMM_SMEM_BYTES>>>(x, a, N);
    k_deg<<<(ET + 255) / 256, 256>>>(ei, E, ET);
    k_scan1<<<NB, 1024>>>(N);
    k_scan2<<<1, 64>>>(NB);
    k_scan3<<<NB, 1024>>>(N, ET);
    k_scatter<<<(ET + 255) / 256, 256>>>(ei, E, ET);
    k_gather<<<(N + 7) / 8, 256>>>(out, N);
}

// round 8
// speedup vs baseline: 2.4331x; 1.0781x over previous
#include <cuda_runtime.h>
#include <cuda_bf16.h>
#include <math.h>

// ---------------------------------------------------------------------------
// GAT layer on GB300.
//  msg = x @ W^T  (tf32x2 tensor-core GEMM, W pre-converted to mma fragments
//                  held in L1 via LDG — no SMEM staging, higher occupancy)
//  s_src = msg@a[:F], s_dst = msg@a[F:]  (fused into GEMM epilogue)
//  CSR-by-dst build (histogram -> multi-block scan -> counting sort)
//  warp-per-node gather (no float atomics)
// ---------------------------------------------------------------------------

#define MAXN   50048
#define MAXE   600064
#define MAXET  (MAXN + MAXE)
#define F      128
#define PAD    132

__device__ float  g_msg[(size_t)MAXN * F];
__device__ float  g_ssrc[MAXN];
__device__ float  g_sdst[MAXN];
__device__ int    g_deg[MAXN];
__device__ int    g_off[MAXN + 1];
__device__ int    g_cur[MAXN];
__device__ float2 g_sw[MAXET];           // packed (src_bits, w)
__device__ int    g_bsum[64];
__device__ int    g_is64;
__device__ uint4  g_bfrag[16 * 16 * 32]; // per-(ka,j,lane) B fragments

// ---------------- tf32 helpers ---------------------------------------------
__device__ __forceinline__ unsigned f2tf(float f) {
    unsigned u;
    asm("cvt.rna.tf32.f32 %0, %1;" : "=r"(u) : "f"(f));
    return u;
}

__device__ __forceinline__ void mma8(float* c,
                                     unsigned a0, unsigned a1, unsigned a2, unsigned a3,
                                     unsigned b0, unsigned b1) {
    asm volatile(
        "mma.sync.aligned.m16n8k8.row.col.f32.tf32.tf32.f32 "
        "{%0,%1,%2,%3}, {%4,%5,%6,%7}, {%8,%9}, {%0,%1,%2,%3};\n"
        : "+f"(c[0]), "+f"(c[1]), "+f"(c[2]), "+f"(c[3])
        : "r"(a0), "r"(a1), "r"(a2), "r"(a3), "r"(b0), "r"(b1));
}

// ---------------- init: zero histogram + dtype detect + W fragment cvt -----
__global__ void k_init(const int* __restrict__ ei32, const float* __restrict__ W,
                       int N) {
    __shared__ int sh[256];
    int i = blockIdx.x * blockDim.x + threadIdx.x;
    if (i < N) g_deg[i] = 0;
    // W -> tf32x2 mma fragments (first 8192 threads)
    if (i < 16 * 16 * 32) {
        int lane = i & 31, j = (i >> 5) & 15, ka = i >> 9;
        int g = lane >> 2, tg = lane & 3;
        float b0 = W[(8 * j + g) * F + 8 * ka + tg];
        float b1 = W[(8 * j + g) * F + 8 * ka + tg + 4];
        unsigned bh0 = f2tf(b0), bh1 = f2tf(b1);
        unsigned bl0 = f2tf(b0 - __uint_as_float(bh0));
        unsigned bl1 = f2tf(b1 - __uint_as_float(bh1));
        g_bfrag[i] = make_uint4(bh0, bh1, bl0, bl1);
    }
    if (blockIdx.x == 0) {
        int any = 0;
        for (int t = threadIdx.x; t < 512; t += 256) any |= ei32[2 * t + 1];
        sh[threadIdx.x] = any;
        __syncthreads();
        for (int s = 128; s > 0; s >>= 1) {
            if (threadIdx.x < s) sh[threadIdx.x] |= sh[threadIdx.x + s];
            __syncthreads();
        }
        if (threadIdx.x == 0) g_is64 = (sh[0] == 0) ? 1 : 0;
    }
}

__device__ __forceinline__ void load_edge(const void* ei, int E, int e,
                                          int& src, int& dst) {
    if (g_is64) {
        const long long* p = (const long long*)ei;
        src = (int)p[e];
        dst = (int)p[E + e];
    } else {
        const int* p = (const int*)ei;
        src = p[e];
        dst = p[E + e];
    }
}

// ---------------- GEMM: msg = x @ W^T (tf32x2), + s_src/s_dst --------------
// Block: 128 nodes x 128 feats, 256 threads (8 warps), each warp 16 rows.
// SMEM: x tile only (reused for output staging); B fragments via LDG/L1.
#define GEMM_SMEM_BYTES ((F * PAD + 2 * F) * (int)sizeof(float))

__global__ void __launch_bounds__(256) k_gemm(const float* __restrict__ x,
                                              const float* __restrict__ a, int N) {
    extern __shared__ float smem[];
    float* As = smem;               // F x PAD
    float* av = smem + F * PAD;     // 2F floats

    const int tid  = threadIdx.x;
    const int warp = tid >> 5;
    const int lane = tid & 31;
    const int g    = lane >> 2;      // 0..7
    const int tg   = lane & 3;       // 0..3
    const int m0   = blockIdx.x * 128;

    if (tid < 256) av[tid] = a[tid];
    for (int idx = tid; idx < F * 32; idx += 256) {
        int r = idx >> 5, c4 = idx & 31;
        int row = m0 + r;
        float4 v = (row < N) ? ((const float4*)x)[(size_t)row * 32 + c4]
                             : make_float4(0.f, 0.f, 0.f, 0.f);
        *(float4*)&As[r * PAD + c4 * 4] = v;
    }
    __syncthreads();

    float acc[16][4];
    #pragma unroll
    for (int j = 0; j < 16; ++j)
        acc[j][0] = acc[j][1] = acc[j][2] = acc[j][3] = 0.f;

    const int mw = warp * 16;
    const uint4* __restrict__ bf = g_bfrag + lane;

    #pragma unroll
    for (int ka = 0; ka < 16; ++ka) {
        const int k0 = ka * 8;
        float a0f = As[(mw + g)     * PAD + k0 + tg];
        float a1f = As[(mw + g + 8) * PAD + k0 + tg];
        float a2f = As[(mw + g)     * PAD + k0 + tg + 4];
        float a3f = As[(mw + g + 8) * PAD + k0 + tg + 4];
        unsigned ah0 = f2tf(a0f), ah1 = f2tf(a1f), ah2 = f2tf(a2f), ah3 = f2tf(a3f);
        unsigned al0 = f2tf(a0f - __uint_as_float(ah0));
        unsigned al1 = f2tf(a1f - __uint_as_float(ah1));
        unsigned al2 = f2tf(a2f - __uint_as_float(ah2));
        unsigned al3 = f2tf(a3f - __uint_as_float(ah3));

        #pragma unroll
        for (int j = 0; j < 16; ++j) {
            uint4 b = __ldg(bf + (ka * 16 + j) * 32);
            mma8(acc[j], ah0, ah1, ah2, ah3, b.x, b.y);  // hi*hi
            mma8(acc[j], ah0, ah1, ah2, ah3, b.z, b.w);  // hi*lo
            mma8(acc[j], al0, al1, al2, al3, b.x, b.y);  // lo*hi
        }
    }

    // ---- fused attention scores: s = msg @ a -------------------------------
    float p0 = 0.f, q0 = 0.f, p1 = 0.f, q1 = 0.f;  // rows g, g+8
    #pragma unroll
    for (int j = 0; j < 16; ++j) {
        int c = 8 * j + 2 * tg;
        p0 += acc[j][0] * av[c]       + acc[j][1] * av[c + 1];
        q0 += acc[j][0] * av[F + c]   + acc[j][1] * av[F + c + 1];
        p1 += acc[j][2] * av[c]       + acc[j][3] * av[c + 1];
        q1 += acc[j][2] * av[F + c]   + acc[j][3] * av[F + c + 1];
    }
    #pragma unroll
    for (int off = 1; off < 4; off <<= 1) {
        p0 += __shfl_xor_sync(0xffffffffu, p0, off);
        q0 += __shfl_xor_sync(0xffffffffu, q0, off);
        p1 += __shfl_xor_sync(0xffffffffu, p1, off);
        q1 += __shfl_xor_sync(0xffffffffu, q1, off);
    }
    if (tg == 0) {
        int r0 = m0 + mw + g, r1 = r0 + 8;
        if (r0 < N) { g_ssrc[r0] = p0; g_sdst[r0] = q0; }
        if (r1 < N) { g_ssrc[r1] = p1; g_sdst[r1] = q1; }
    }

    // ---- stage accumulators to (warp-private) SMEM, store coalesced --------
    __syncwarp();
    #pragma unroll
    for (int j = 0; j < 16; ++j) {
        int c = 8 * j + 2 * tg;
        *(float2*)&As[(mw + g)     * PAD + c] = make_float2(acc[j][0], acc[j][1]);
        *(float2*)&As[(mw + g + 8) * PAD + c] = make_float2(acc[j][2], acc[j][3]);
    }
    __syncwarp();
    for (int idx = lane; idx < 512; idx += 32) {
        int r = idx >> 5, c4 = idx & 31;
        int row = m0 + mw + r;
        if (row < N)
            *(float4*)&g_msg[(size_t)row * F + c4 * 4] =
                *(float4*)&As[(mw + r) * PAD + c4 * 4];
    }
}

// ---------------- CSR build ------------------------------------------------
__global__ void k_deg(const void* ei, int E, int ET) {
    int e = blockIdx.x * blockDim.x + threadIdx.x;
    if (e >= ET) return;
    int dst;
    if (e < E) {
        dst = g_is64 ? (int)((const long long*)ei)[E + e]
                     : ((const int*)ei)[E + e];
    } else {
        dst = e - E;
    }
    atomicAdd(&g_deg[dst], 1);
}

// Multi-block scan, pass 1: per-block local exclusive scan + block totals.
__global__ void k_scan1(int n) {
    __shared__ int wsum[32];
    const int tid = threadIdx.x, lane = tid & 31, warp = tid >> 5;
    const int i = blockIdx.x * 1024 + tid;
    int v = (i < n) ? g_deg[i] : 0;
    int s = v;
    #pragma unroll
    for (int off = 1; off < 32; off <<= 1) {
        int t = __shfl_up_sync(0xffffffffu, s, off);
        if (lane >= off) s += t;
    }
    if (lane == 31) wsum[warp] = s;
    __syncthreads();
    if (warp == 0) {
        int ws = wsum[lane];
        #pragma unroll
        for (int off = 1; off < 32; off <<= 1) {
            int t = __shfl_up_sync(0xffffffffu, ws, off);
            if (lane >= off) ws += t;
        }
        wsum[lane] = ws;
    }
    __syncthreads();
    int excl = (warp ? wsum[warp - 1] : 0) + s - v;
    if (i < n) g_off[i] = excl;
    if (tid == 0) g_bsum[blockIdx.x] = wsum[31];
}

// Pass 2: exclusive scan of (<=64) block totals, one block.
__global__ void k_scan2(int nb) {
    __shared__ int sh[64];
    int tid = threadIdx.x;
    int v = (tid < nb) ? g_bsum[tid] : 0;
    sh[tid] = v;
    __syncthreads();
    #pragma unroll
    for (int off = 1; off < 64; off <<= 1) {
        int t = (tid >= off) ? sh[tid - off] : 0;
        __syncthreads();
        sh[tid] += t;
        __syncthreads();
    }
    if (tid < nb) g_bsum[tid] = sh[tid] - v;
}

// Pass 3: add block offsets, init cursors.
__global__ void k_scan3(int n, int total) {
    int i = blockIdx.x * 1024 + threadIdx.x;
    if (i < n) {
        int o = g_off[i] + g_bsum[blockIdx.x];
        g_off[i] = o;
        g_cur[i] = o;
    }
    if (i == 0) g_off[n] = total;
}

__global__ void k_scatter(const void* ei, int E, int ET) {
    int e = blockIdx.x * blockDim.x + threadIdx.x;
    if (e >= ET) return;
    int src, dst;
    if (e < E) load_edge(ei, E, e, src, dst);
    else       src = dst = e - E;
    float s  = g_ssrc[src] + g_sdst[dst];
    float lr = (s > 0.f) ? s : 0.01f * s;
    float w  = expf(lr);
    int pos = atomicAdd(&g_cur[dst], 1);
    g_sw[pos] = make_float2(__int_as_float(src), w);
}

// ---------------- gather: one warp per dst node ----------------------------
__global__ void k_gather(float* __restrict__ out, int N) {
    int gw   = (blockIdx.x * blockDim.x + threadIdx.x) >> 5;
    int lane = threadIdx.x & 31;
    if (gw >= N) return;
    int beg = g_off[gw];
    int end = g_off[gw + 1];
    float4 acc = make_float4(0.f, 0.f, 0.f, 0.f);
    float denom = 0.f;
    int e = beg;
    for (; e + 2 <= end; e += 2) {
        float2 sw0 = g_sw[e], sw1 = g_sw[e + 1];
        int   s0 = __float_as_int(sw0.x), s1 = __float_as_int(sw1.x);
        float w0 = sw0.y,                 w1 = sw1.y;
        const float4 m0 = *(const float4*)&g_msg[(size_t)s0 * F + lane * 4];
        const float4 m1 = *(const float4*)&g_msg[(size_t)s1 * F + lane * 4];
        denom += w0 + w1;
        acc.x += w0 * m0.x + w1 * m1.x;
        acc.y += w0 * m0.y + w1 * m1.y;
        acc.z += w0 * m0.z + w1 * m1.z;
        acc.w += w0 * m0.w + w1 * m1.w;
    }
    if (e < end) {
        float2 sw0 = g_sw[e];
        int   s0 = __float_as_int(sw0.x);
        float w0 = sw0.y;
        const float4 m0 = *(const float4*)&g_msg[(size_t)s0 * F + lane * 4];
        denom += w0;
        acc.x += w0 * m0.x; acc.y += w0 * m0.y;
        acc.z += w0 * m0.z; acc.w += w0 * m0.w;
    }
    float inv = 1.f / fmaxf(denom, 1e-12f);
    float4 o = make_float4(acc.x * inv, acc.y * inv, acc.z * inv, acc.w * inv);
    *reinterpret_cast<float4*>(&out[(size_t)gw * F + lane * 4]) = o;
}

// ---------------------------------------------------------------------------
extern "C" void kernel_launch(void* const* d_in, const int* in_sizes, int n_in,
                              void* d_out, int out_size) {
    const float* x  = (const float*)d_in[0];
    const void*  ei = d_in[1];
    const float* W  = (const float*)d_in[2];
    const float* a  = (const float*)d_in[3];
    float* out = (float*)d_out;

    int N  = in_sizes[0] / F;
    int E  = in_sizes[1] / 2;
    int ET = E + N;
    int NB = (N + 1023) / 1024;

    cudaFuncSetAttribute(k_gemm, cudaFuncAttributeMaxDynamicSharedMemorySize,
                         GEMM_SMEM_BYTES);

    k_init<<<(N + 255) / 256, 256>>>((const int*)ei, W, N);
    k_gemm<<<(N + 127) / 128, 256, GEMM_SMEM_BYTES>>>(x, a, N);
    k_deg<<<(ET + 255) / 256, 256>>>(ei, E, ET);
    k_scan1<<<NB, 1024>>>(N);
    k_scan2<<<1, 64>>>(NB);
    k_scan3<<<NB, 1024>>>(N, ET);
    k_scatter<<<(ET + 255) / 256, 256>>>(ei, E, ET);
    k_gather<<<(N + 7) / 8, 256>>>(out, N);
}

// round 11
// speedup vs baseline: 2.7448x; 1.1281x over previous
#include <cuda_runtime.h>
#include <cuda_bf16.h>
#include <math.h>

// ---------------------------------------------------------------------------
// GAT layer on GB300.
//  msg = x @ W^T  (bf16x2 tensor-core GEMM m16n8k16, W pre-converted to
//                  packed mma fragments held in L1 via LDG)
//  s_src = msg@a[:F], s_dst = msg@a[F:]  (fused into GEMM epilogue)
//  CSR-by-dst build (histogram -> decoupled-lookback scan -> counting sort)
//  warp-per-node gather (no float atomics)
// ---------------------------------------------------------------------------

#define MAXN   50048
#define MAXE   600064
#define MAXET  (MAXN + MAXE)
#define F      128
#define PAD    132
#define NFRAG  (8 * 16 * 32)   // (ka, j, lane) bf16 B fragments

__device__ float  g_msg[(size_t)MAXN * F];
__device__ float  g_ssrc[MAXN];
__device__ float  g_sdst[MAXN];
__device__ int    g_deg[MAXN];
__device__ int    g_off[MAXN + 1];
__device__ int    g_cur[MAXN];
__device__ float2 g_sw[MAXET];            // packed (src_bits, w)
__device__ unsigned long long g_lbk[64];  // lookback: (state<<32)|aggregate
__device__ int    g_is64;
__device__ uint4  g_bfrag[NFRAG];         // (bh0,bh1,bl0,bl1) per (ka,j,lane)

// ---------------- init: zero hist/lookback + dtype detect + W frag cvt -----
__global__ void k_init(const int* __restrict__ ei32, const float* __restrict__ W,
                       int N) {
    __shared__ int sh[256];
    int i = blockIdx.x * blockDim.x + threadIdx.x;
    if (i < N) g_deg[i] = 0;
    if (i < 64) g_lbk[i] = 0ull;
    // W -> bf16x2 mma fragments (first 4096 threads)
    if (i < NFRAG) {
        int lane = i & 31, j = (i >> 5) & 15, ka = i >> 9;   // ka 0..7
        int g = lane >> 2, tg = lane & 3;
        int row = 8 * j + g, k0 = 16 * ka;
        float f0 = W[row * F + k0 + 2 * tg];
        float f1 = W[row * F + k0 + 2 * tg + 1];
        float f2 = W[row * F + k0 + 2 * tg + 8];
        float f3 = W[row * F + k0 + 2 * tg + 9];
        __nv_bfloat162 h0 = __floats2bfloat162_rn(f0, f1);
        __nv_bfloat162 h1 = __floats2bfloat162_rn(f2, f3);
        __nv_bfloat162 l0 = __floats2bfloat162_rn(f0 - __bfloat162float(h0.x),
                                                  f1 - __bfloat162float(h0.y));
        __nv_bfloat162 l1 = __floats2bfloat162_rn(f2 - __bfloat162float(h1.x),
                                                  f3 - __bfloat162float(h1.y));
        g_bfrag[i] = make_uint4(*(unsigned*)&h0, *(unsigned*)&h1,
                                *(unsigned*)&l0, *(unsigned*)&l1);
    }
    if (blockIdx.x == 0) {
        int any = 0;
        for (int t = threadIdx.x; t < 512; t += 256) any |= ei32[2 * t + 1];
        sh[threadIdx.x] = any;
        __syncthreads();
        for (int s = 128; s > 0; s >>= 1) {
            if (threadIdx.x < s) sh[threadIdx.x] |= sh[threadIdx.x + s];
            __syncthreads();
        }
        if (threadIdx.x == 0) g_is64 = (sh[0] == 0) ? 1 : 0;
    }
}

__device__ __forceinline__ void load_edge(const void* ei, int E, int e,
                                          int& src, int& dst) {
    if (g_is64) {
        const long long* p = (const long long*)ei;
        src = (int)p[e];
        dst = (int)p[E + e];
    } else {
        const int* p = (const int*)ei;
        src = p[e];
        dst = p[E + e];
    }
}

// ---------------- bf16 mma -------------------------------------------------
__device__ __forceinline__ void mma16(float* c,
                                      unsigned a0, unsigned a1, unsigned a2, unsigned a3,
                                      unsigned b0, unsigned b1) {
    asm volatile(
        "mma.sync.aligned.m16n8k16.row.col.f32.bf16.bf16.f32 "
        "{%0,%1,%2,%3}, {%4,%5,%6,%7}, {%8,%9}, {%0,%1,%2,%3};\n"
        : "+f"(c[0]), "+f"(c[1]), "+f"(c[2]), "+f"(c[3])
        : "r"(a0), "r"(a1), "r"(a2), "r"(a3), "r"(b0), "r"(b1));
}

// ---------------- GEMM: msg = x @ W^T (bf16x2), + s_src/s_dst --------------
// Block: 128 nodes x 128 feats, 256 threads (8 warps), each warp 16 rows.
#define GEMM_SMEM_BYTES ((F * PAD + 2 * F) * (int)sizeof(float))

__global__ void __launch_bounds__(256) k_gemm(const float* __restrict__ x,
                                              const float* __restrict__ a, int N) {
    extern __shared__ float smem[];
    float* As = smem;               // F x PAD
    float* av = smem + F * PAD;     // 2F floats

    const int tid  = threadIdx.x;
    const int warp = tid >> 5;
    const int lane = tid & 31;
    const int g    = lane >> 2;      // 0..7
    const int tg   = lane & 3;       // 0..3
    const int m0   = blockIdx.x * 128;

    if (tid < 256) av[tid] = a[tid];
    for (int idx = tid; idx < F * 32; idx += 256) {
        int r = idx >> 5, c4 = idx & 31;
        int row = m0 + r;
        float4 v = (row < N) ? ((const float4*)x)[(size_t)row * 32 + c4]
                             : make_float4(0.f, 0.f, 0.f, 0.f);
        *(float4*)&As[r * PAD + c4 * 4] = v;
    }
    __syncthreads();

    float acc[16][4];
    #pragma unroll
    for (int j = 0; j < 16; ++j)
        acc[j][0] = acc[j][1] = acc[j][2] = acc[j][3] = 0.f;

    const int mw  = warp * 16;
    const int r0i = (mw + g) * PAD;
    const int r1i = (mw + g + 8) * PAD;
    const uint4* __restrict__ bf = g_bfrag + lane;

    #pragma unroll
    for (int ka = 0; ka < 8; ++ka) {
        const int k0 = ka * 16 + 2 * tg;
        float2 p00 = *(const float2*)&As[r0i + k0];
        float2 p01 = *(const float2*)&As[r0i + k0 + 8];
        float2 p10 = *(const float2*)&As[r1i + k0];
        float2 p11 = *(const float2*)&As[r1i + k0 + 8];

        __nv_bfloat162 h0 = __floats2bfloat162_rn(p00.x, p00.y);
        __nv_bfloat162 h1 = __floats2bfloat162_rn(p10.x, p10.y);
        __nv_bfloat162 h2 = __floats2bfloat162_rn(p01.x, p01.y);
        __nv_bfloat162 h3 = __floats2bfloat162_rn(p11.x, p11.y);
        __nv_bfloat162 l0 = __floats2bfloat162_rn(p00.x - __bfloat162float(h0.x),
                                                  p00.y - __bfloat162float(h0.y));
        __nv_bfloat162 l1 = __floats2bfloat162_rn(p10.x - __bfloat162float(h1.x),
                                                  p10.y - __bfloat162float(h1.y));
        __nv_bfloat162 l2 = __floats2bfloat162_rn(p01.x - __bfloat162float(h2.x),
                                                  p01.y - __bfloat162float(h2.y));
        __nv_bfloat162 l3 = __floats2bfloat162_rn(p11.x - __bfloat162float(h3.x),
                                                  p11.y - __bfloat162float(h3.y));
        unsigned ah0 = *(unsigned*)&h0, ah1 = *(unsigned*)&h1;
        unsigned ah2 = *(unsigned*)&h2, ah3 = *(unsigned*)&h3;
        unsigned al0 = *(unsigned*)&l0, al1 = *(unsigned*)&l1;
        unsigned al2 = *(unsigned*)&l2, al3 = *(unsigned*)&l3;

        #pragma unroll
        for (int j = 0; j < 16; ++j) {
            uint4 b = __ldg(bf + (ka * 16 + j) * 32);
            mma16(acc[j], ah0, ah1, ah2, ah3, b.x, b.y);  // hi*hi
            mma16(acc[j], ah0, ah1, ah2, ah3, b.z, b.w);  // hi*lo
            mma16(acc[j], al0, al1, al2, al3, b.x, b.y);  // lo*hi
        }
    }

    // ---- fused attention scores: s = msg @ a -------------------------------
    float p0 = 0.f, q0 = 0.f, p1 = 0.f, q1 = 0.f;  // rows g, g+8
    #pragma unroll
    for (int j = 0; j < 16; ++j) {
        int c = 8 * j + 2 * tg;
        p0 += acc[j][0] * av[c]       + acc[j][1] * av[c + 1];
        q0 += acc[j][0] * av[F + c]   + acc[j][1] * av[F + c + 1];
        p1 += acc[j][2] * av[c]       + acc[j][3] * av[c + 1];
        q1 += acc[j][2] * av[F + c]   + acc[j][3] * av[F + c + 1];
    }
    #pragma unroll
    for (int off = 1; off < 4; off <<= 1) {
        p0 += __shfl_xor_sync(0xffffffffu, p0, off);
        q0 += __shfl_xor_sync(0xffffffffu, q0, off);
        p1 += __shfl_xor_sync(0xffffffffu, p1, off);
        q1 += __shfl_xor_sync(0xffffffffu, q1, off);
    }
    if (tg == 0) {
        int r0 = m0 + mw + g, r1 = r0 + 8;
        if (r0 < N) { g_ssrc[r0] = p0; g_sdst[r0] = q0; }
        if (r1 < N) { g_ssrc[r1] = p1; g_sdst[r1] = q1; }
    }

    // ---- stage accumulators to (warp-private) SMEM, store coalesced --------
    __syncwarp();
    #pragma unroll
    for (int j = 0; j < 16; ++j) {
        int c = 8 * j + 2 * tg;
        *(float2*)&As[r0i + c] = make_float2(acc[j][0], acc[j][1]);
        *(float2*)&As[r1i + c] = make_float2(acc[j][2], acc[j][3]);
    }
    __syncwarp();
    for (int idx = lane; idx < 512; idx += 32) {
        int r = idx >> 5, c4 = idx & 31;
        int row = m0 + mw + r;
        if (row < N)
            *(float4*)&g_msg[(size_t)row * F + c4 * 4] =
                *(float4*)&As[(mw + r) * PAD + c4 * 4];
    }
}

// ---------------- CSR build ------------------------------------------------
__global__ void k_deg(const void* ei, int E, int ET) {
    int e = blockIdx.x * blockDim.x + threadIdx.x;
    if (e >= ET) return;
    int dst;
    if (e < E) {
        dst = g_is64 ? (int)((const long long*)ei)[E + e]
                     : ((const int*)ei)[E + e];
    } else {
        dst = e - E;
    }
    atomicAdd(&g_deg[dst], 1);
}

// Single-kernel decoupled-lookback exclusive scan of g_deg -> g_off/g_cur.
__global__ void k_scan(int n, int total) {
    __shared__ int wsum[32];
    __shared__ int s_prefix;
    const int tid = threadIdx.x, lane = tid & 31, warp = tid >> 5;
    const int b = blockIdx.x;
    const int i = b * 1024 + tid;
    int v = (i < n) ? g_deg[i] : 0;
    int s = v;
    #pragma unroll
    for (int off = 1; off < 32; off <<= 1) {
        int t = __shfl_up_sync(0xffffffffu, s, off);
        if (lane >= off) s += t;
    }
    if (lane == 31) wsum[warp] = s;
    __syncthreads();
    if (warp == 0) {
        int ws = wsum[lane];
        #pragma unroll
        for (int off = 1; off < 32; off <<= 1) {
            int t = __shfl_up_sync(0xffffffffu, ws, off);
            if (lane >= off) ws += t;
        }
        wsum[lane] = ws;
    }
    __syncthreads();
    int agg = wsum[31];

    if (tid == 0) {
        if (b == 0) {
            atomicExch(&g_lbk[0], (2ull << 32) | (unsigned)agg);
            s_prefix = 0;
        } else {
            atomicExch(&g_lbk[b], (1ull << 32) | (unsigned)agg);
            int prefix = 0;
            int p = b - 1;
            while (true) {
                unsigned long long val = *(volatile unsigned long long*)&g_lbk[p];
                unsigned st = (unsigned)(val >> 32);
                if (st == 0) continue;
                prefix += (int)(unsigned)val;
                if (st == 2) break;
                --p;
            }
            atomicExch(&g_lbk[b], (2ull << 32) | (unsigned)(prefix + agg));
            s_prefix = prefix;
        }
    }
    __syncthreads();
    int excl = s_prefix + (warp ? wsum[warp - 1] : 0) + s - v;
    if (i < n) { g_off[i] = excl; g_cur[i] = excl; }
    if (i == 0) g_off[n] = total;
}

__global__ void k_scatter(const void* ei, int E, int ET) {
    int e = blockIdx.x * blockDim.x + threadIdx.x;
    if (e >= ET) return;
    int src, dst;
    if (e < E) load_edge(ei, E, e, src, dst);
    else       src = dst = e - E;
    float s  = g_ssrc[src] + g_sdst[dst];
    float lr = (s > 0.f) ? s : 0.01f * s;
    float w  = expf(lr);
    int pos = atomicAdd(&g_cur[dst], 1);
    g_sw[pos] = make_float2(__int_as_float(src), w);
}

// ---------------- gather: one warp per dst node ----------------------------
__global__ void k_gather(float* __restrict__ out, int N) {
    int gw   = (blockIdx.x * blockDim.x + threadIdx.x) >> 5;
    int lane = threadIdx.x & 31;
    if (gw >= N) return;
    int beg = g_off[gw];
    int end = g_off[gw + 1];
    float4 acc = make_float4(0.f, 0.f, 0.f, 0.f);
    float denom = 0.f;
    int e = beg;
    for (; e + 4 <= end; e += 4) {
        float2 sw0 = g_sw[e],     sw1 = g_sw[e + 1];
        float2 sw2 = g_sw[e + 2], sw3 = g_sw[e + 3];
        const float4 m0 = *(const float4*)&g_msg[(size_t)__float_as_int(sw0.x) * F + lane * 4];
        const float4 m1 = *(const float4*)&g_msg[(size_t)__float_as_int(sw1.x) * F + lane * 4];
        const float4 m2 = *(const float4*)&g_msg[(size_t)__float_as_int(sw2.x) * F + lane * 4];
        const float4 m3 = *(const float4*)&g_msg[(size_t)__float_as_int(sw3.x) * F + lane * 4];
        float w0 = sw0.y, w1 = sw1.y, w2 = sw2.y, w3 = sw3.y;
        denom += (w0 + w1) + (w2 + w3);
        acc.x += w0 * m0.x + w1 * m1.x + w2 * m2.x + w3 * m3.x;
        acc.y += w0 * m0.y + w1 * m1.y + w2 * m2.y + w3 * m3.y;
        acc.z += w0 * m0.z + w1 * m1.z + w2 * m2.z + w3 * m3.z;
        acc.w += w0 * m0.w + w1 * m1.w + w2 * m2.w + w3 * m3.w;
    }
    for (; e < end; ++e) {
        float2 sw0 = g_sw[e];
        float w0 = sw0.y;
        const float4 m0 = *(const float4*)&g_msg[(size_t)__float_as_int(sw0.x) * F + lane * 4];
        denom += w0;
        acc.x += w0 * m0.x; acc.y += w0 * m0.y;
        acc.z += w0 * m0.z; acc.w += w0 * m0.w;
    }
    float inv = 1.f / fmaxf(denom, 1e-12f);
    float4 o = make_float4(acc.x * inv, acc.y * inv, acc.z * inv, acc.w * inv);
    *reinterpret_cast<float4*>(&out[(size_t)gw * F + lane * 4]) = o;
}

// ---------------------------------------------------------------------------
extern "C" void kernel_launch(void* const* d_in, const int* in_sizes, int n_in,
                              void* d_out, int out_size) {
    const float* x  = (const float*)d_in[0];
    const void*  ei = d_in[1];
    const float* W  = (const float*)d_in[2];
    const float* a  = (const float*)d_in[3];
    float* out = (float*)d_out;

    int N  = in_sizes[0] / F;
    int E  = in_sizes[1] / 2;
    int ET = E + N;
    int NB = (N + 1023) / 1024;

    cudaFuncSetAttribute(k_gemm, cudaFuncAttributeMaxDynamicSharedMemorySize,
                         GEMM_SMEM_BYTES);

    k_init<<<(N + 255) / 256, 256>>>((const int*)ei, W, N);
    k_gemm<<<(N + 127) / 128, 256, GEMM_SMEM_BYTES>>>(x, a, N);
    k_deg<<<(ET + 255) / 256, 256>>>(ei, E, ET);
    k_scan<<<NB, 1024>>>(N, ET);
    k_scatter<<<(ET + 255) / 256, 256>>>(ei, E, ET);
    k_gather<<<(N + 7) / 8, 256>>>(out, N);
}